// round 6
// baseline (speedup 1.0000x reference)
#include <cuda_runtime.h>
#include <cuda_bf16.h>
#include <math.h>

// Problem constants
#define Bdim 4
#define Sdim 1024
#define Edim 512
#define NHdim 8
#define Ddim 64
#define NTOK (Bdim * Sdim)        // 4096
#define E4 (4 * Edim)             // 2048

// ---------------- scratch (device globals; allocation-free) ----------------
__device__ float g_q[NTOK * Edim];
__device__ float g_k[NTOK * Edim];
__device__ float g_v[NTOK * Edim];
__device__ float g_q2[NTOK * Edim];
__device__ float g_k2[NTOK * Edim];
__device__ float g_v2[NTOK * Edim];
__device__ float g_attn[NTOK * Edim];
__device__ float g_attn2[NTOK * Edim];
__device__ float g_proj[NTOK * Edim];
__device__ float g_proj2[NTOK * Edim];
__device__ float g_body1[NTOK * Edim];
__device__ float g_limb1[NTOK * Edim];
__device__ float g_bcross[NTOK * Edim];
__device__ float g_lcross[NTOK * Edim];
__device__ float g_body2[NTOK * Edim];
__device__ float g_limb2[NTOK * Edim];
__device__ float g_mid[NTOK * E4];
__device__ float g_mid2[NTOK * E4];

// ---------------- helpers ----------------
__device__ __forceinline__ float read_temp(const void* p) {
    int iv = *(const int*)p;
    float fv = __int_as_float(iv);
    if (iv > 0 && iv < 0x00800000) return (float)iv;  // int bit pattern
    return fv;
}

__device__ __forceinline__ unsigned f2tf32(float f) {
    unsigned u;
    asm("cvt.rna.tf32.f32 %0, %1;" : "=r"(u) : "f"(f));
    return u;
}

__device__ __forceinline__ void cp16(void* dst, const void* src) {
    unsigned d = (unsigned)__cvta_generic_to_shared(dst);
    asm volatile("cp.async.cg.shared.global [%0], [%1], 16;\n" :: "r"(d), "l"(src));
}
__device__ __forceinline__ void cp_commit() {
    asm volatile("cp.async.commit_group;\n");
}
template<int N> __device__ __forceinline__ void cp_wait() {
    asm volatile("cp.async.wait_group %0;\n" :: "n"(N));
}

// reduce two values across a 128-thread block (4 warps)
__device__ __forceinline__ void block_sum2_128(float& a, float& b, float* red) {
    #pragma unroll
    for (int s = 16; s > 0; s >>= 1) {
        a += __shfl_xor_sync(0xffffffffu, a, s);
        b += __shfl_xor_sync(0xffffffffu, b, s);
    }
    int wid = threadIdx.x >> 5, lane = threadIdx.x & 31;
    if (lane == 0) { red[wid] = a; red[4 + wid] = b; }
    __syncthreads();
    a = red[0] + red[1] + red[2] + red[3];
    b = red[4] + red[5] + red[6] + red[7];
    __syncthreads();
}

#define MMA_TF32(ACC, AF, B0, B1)                                              \
    asm volatile(                                                              \
        "mma.sync.aligned.m16n8k8.row.col.f32.tf32.tf32.f32 "                  \
        "{%0,%1,%2,%3}, {%4,%5,%6,%7}, {%8,%9}, {%0,%1,%2,%3};\n"              \
        : "+f"((ACC)[0]), "+f"((ACC)[1]), "+f"((ACC)[2]), "+f"((ACC)[3])       \
        : "r"((AF)[0]), "r"((AF)[1]), "r"((AF)[2]), "r"((AF)[3]),              \
          "r"(B0), "r"(B1))

// ---------------- batched TF32 GEMM: C[M,N] = A @ W + bias (+opt GELU) ----------------
// Template BM: 128 (256 thr, 8 warps 4Mx2N) or 64 (128 thr, 4 warps 2Mx2N).
// Warp tile 32x64. BK=32, double-buffered cp.async.
struct GemmB { const float* A; const float* W; const float* bias; float* C; };
struct GemmB6 { GemmB g[6]; };

#define GLA 36
#define GLB 136

template<int BM>
__global__ __launch_bounds__(256) void gemm_tc(
    GemmB6 batch, int M, int N, int K, int act)
{
    constexpr int NT = (BM == 128) ? 256 : 128;
    constexpr int BUF = BM * GLA + 32 * GLB;
    constexpr int A_STRIDE = NT / 8;     // rows per staging iter
    constexpr int B_IT = 1024 / NT;      // B float4 iters
    constexpr int B_STRIDE = NT / 32;    // k-rows per staging iter

    extern __shared__ float sm[];
    GemmB gp = batch.g[blockIdx.z];
    const float* __restrict__ A = gp.A;
    const float* __restrict__ W = gp.W;

    int tid = threadIdx.x;
    int lane = tid & 31;
    int warp = tid >> 5;
    int g = lane >> 2;
    int tig = lane & 3;

    int row0 = blockIdx.y * BM;
    int col0 = blockIdx.x * 128;
    int wm0 = (warp >> 1) * 32;
    int wn0 = (warp & 1) * 64;

    float acc[2][8][4];
    #pragma unroll
    for (int mf = 0; mf < 2; mf++)
        #pragma unroll
        for (int nf = 0; nf < 8; nf++)
            #pragma unroll
            for (int r = 0; r < 4; r++) acc[mf][nf][r] = 0.f;

    int a_r = tid >> 3, a_c4 = tid & 7;
    int b_k = tid >> 5, b_c4 = tid & 31;

    int nkt = K / 32;

    {
        float* as = sm;
        float* bs = sm + BM * GLA;
        #pragma unroll
        for (int it = 0; it < 4; it++)
            cp16(as + (a_r + it * A_STRIDE) * GLA + a_c4 * 4,
                 A + (size_t)(row0 + a_r + it * A_STRIDE) * K + a_c4 * 4);
        #pragma unroll
        for (int it = 0; it < B_IT; it++)
            cp16(bs + (b_k + it * B_STRIDE) * GLB + b_c4 * 4,
                 W + (size_t)(b_k + it * B_STRIDE) * N + col0 + b_c4 * 4);
        cp_commit();
    }

    for (int kt = 0; kt < nkt; kt++) {
        if (kt + 1 < nkt) {
            int k0 = (kt + 1) * 32;
            float* as = sm + ((kt + 1) & 1) * BUF;
            float* bs = as + BM * GLA;
            #pragma unroll
            for (int it = 0; it < 4; it++)
                cp16(as + (a_r + it * A_STRIDE) * GLA + a_c4 * 4,
                     A + (size_t)(row0 + a_r + it * A_STRIDE) * K + k0 + a_c4 * 4);
            #pragma unroll
            for (int it = 0; it < B_IT; it++)
                cp16(bs + (b_k + it * B_STRIDE) * GLB + b_c4 * 4,
                     W + (size_t)(k0 + b_k + it * B_STRIDE) * N + col0 + b_c4 * 4);
            cp_commit();
            cp_wait<1>();
        } else {
            cp_wait<0>();
        }
        __syncthreads();

        const float* as = sm + (kt & 1) * BUF;
        const float* bs = as + BM * GLA;

        #pragma unroll
        for (int ks = 0; ks < 4; ks++) {
            int kk = ks * 8;
            unsigned a_frag[2][4];
            #pragma unroll
            for (int mf = 0; mf < 2; mf++) {
                int rb = wm0 + mf * 16;
                a_frag[mf][0] = __float_as_uint(as[(rb + g) * GLA + kk + tig]);
                a_frag[mf][1] = __float_as_uint(as[(rb + g + 8) * GLA + kk + tig]);
                a_frag[mf][2] = __float_as_uint(as[(rb + g) * GLA + kk + tig + 4]);
                a_frag[mf][3] = __float_as_uint(as[(rb + g + 8) * GLA + kk + tig + 4]);
            }
            unsigned b_frag[8][2];
            #pragma unroll
            for (int nf = 0; nf < 8; nf++) {
                int c = wn0 + nf * 8 + g;
                b_frag[nf][0] = __float_as_uint(bs[(kk + tig) * GLB + c]);
                b_frag[nf][1] = __float_as_uint(bs[(kk + tig + 4) * GLB + c]);
            }
            #pragma unroll
            for (int mf = 0; mf < 2; mf++)
                #pragma unroll
                for (int nf = 0; nf < 8; nf++)
                    MMA_TF32(acc[mf][nf], a_frag[mf], b_frag[nf][0], b_frag[nf][1]);
        }
        __syncthreads();
    }

    const float* bias = gp.bias;
    float* C = gp.C;
    #pragma unroll
    for (int mf = 0; mf < 2; mf++) {
        #pragma unroll
        for (int nf = 0; nf < 8; nf++) {
            int col = col0 + wn0 + nf * 8 + tig * 2;
            float bx = bias[col], by = bias[col + 1];
            float v0 = acc[mf][nf][0] + bx;
            float v1 = acc[mf][nf][1] + by;
            float v2 = acc[mf][nf][2] + bx;
            float v3 = acc[mf][nf][3] + by;
            if (act == 1) {
                v0 = 0.5f * v0 * (1.f + erff(v0 * 0.70710678118f));
                v1 = 0.5f * v1 * (1.f + erff(v1 * 0.70710678118f));
                v2 = 0.5f * v2 * (1.f + erff(v2 * 0.70710678118f));
                v3 = 0.5f * v3 * (1.f + erff(v3 * 0.70710678118f));
            }
            int r = row0 + wm0 + mf * 16 + g;
            *(float2*)(C + (size_t)r * N + col) = make_float2(v0, v1);
            *(float2*)(C + (size_t)(r + 8) * N + col) = make_float2(v2, v3);
        }
    }
}

// ---------------- batched tensor-core flash attention ----------------
struct AttnB { const float* Q; const float* K; const float* V; float* O; };
struct AttnB2 { AttnB a[2]; };

#define KLD 68
#define VLD 72

__global__ __launch_bounds__(128, 4) void attention_tc(
    AttnB2 batch, const void* __restrict__ temp_ptr)
{
    extern __shared__ float sm[];
    AttnB ap = batch.a[blockIdx.z];
    const float* __restrict__ Q = ap.Q;
    const float* __restrict__ K = ap.K;
    const float* __restrict__ V = ap.V;

    int bh = blockIdx.x;
    int b = bh >> 3, h = bh & 7;
    int tid = threadIdx.x, lane = tid & 31, warp = tid >> 5;
    int g = lane >> 2, tig = lane & 3;
    int qr = blockIdx.y * 64 + warp * 16;

    float scale = 0.125f / read_temp(temp_ptr);

    unsigned qf[8][4];
    {
        const float* Qb = Q + ((size_t)(b * Sdim + qr)) * Edim + h * Ddim;
        #pragma unroll
        for (int ks = 0; ks < 8; ks++) {
            qf[ks][0] = f2tf32(Qb[(size_t)g * Edim + ks * 8 + tig] * scale);
            qf[ks][1] = f2tf32(Qb[(size_t)(g + 8) * Edim + ks * 8 + tig] * scale);
            qf[ks][2] = f2tf32(Qb[(size_t)g * Edim + ks * 8 + tig + 4] * scale);
            qf[ks][3] = f2tf32(Qb[(size_t)(g + 8) * Edim + ks * 8 + tig + 4] * scale);
        }
    }

    float oacc[8][4];
    #pragma unroll
    for (int nf = 0; nf < 8; nf++)
        #pragma unroll
        for (int r = 0; r < 4; r++) oacc[nf][r] = 0.f;

    float m_lo = -1e30f, m_hi = -1e30f, l_lo = 0.f, l_hi = 0.f;

    int st_r = tid >> 4;
    int st_c4 = tid & 15;

    {
        float* ks_ = sm;
        float* vs_ = sm + 8704;
        #pragma unroll
        for (int it = 0; it < 8; it++) {
            int r = st_r + it * 8;
            size_t base = ((size_t)(b * Sdim + r)) * Edim + h * Ddim + st_c4 * 4;
            cp16(ks_ + r * KLD + st_c4 * 4, K + base);
            cp16(vs_ + r * VLD + st_c4 * 4, V + base);
        }
        cp_commit();
    }

    const int NKT = Sdim / 64;
    for (int kt = 0; kt < NKT; kt++) {
        if (kt + 1 < NKT) {
            float* ks_ = sm + ((kt + 1) & 1) * 4352;
            float* vs_ = sm + 8704 + ((kt + 1) & 1) * 4608;
            #pragma unroll
            for (int it = 0; it < 8; it++) {
                int r = st_r + it * 8;
                size_t base = ((size_t)(b * Sdim + (kt + 1) * 64 + r)) * Edim + h * Ddim + st_c4 * 4;
                cp16(ks_ + r * KLD + st_c4 * 4, K + base);
                cp16(vs_ + r * VLD + st_c4 * 4, V + base);
            }
            cp_commit();
            cp_wait<1>();
        } else {
            cp_wait<0>();
        }
        __syncthreads();

        const float* ks_ = sm + (kt & 1) * 4352;
        const float* vs_ = sm + 8704 + (kt & 1) * 4608;

        float sacc[8][4];
        #pragma unroll
        for (int nf = 0; nf < 8; nf++) {
            #pragma unroll
            for (int r = 0; r < 4; r++) sacc[nf][r] = 0.f;
            int krow = nf * 8 + g;
            #pragma unroll
            for (int ks = 0; ks < 8; ks++) {
                unsigned b0 = __float_as_uint(ks_[krow * KLD + ks * 8 + tig]);
                unsigned b1 = __float_as_uint(ks_[krow * KLD + ks * 8 + tig + 4]);
                MMA_TF32(sacc[nf], qf[ks], b0, b1);
            }
        }

        float mx_lo = -1e30f, mx_hi = -1e30f;
        #pragma unroll
        for (int nf = 0; nf < 8; nf++) {
            mx_lo = fmaxf(mx_lo, fmaxf(sacc[nf][0], sacc[nf][1]));
            mx_hi = fmaxf(mx_hi, fmaxf(sacc[nf][2], sacc[nf][3]));
        }
        mx_lo = fmaxf(mx_lo, __shfl_xor_sync(0xffffffffu, mx_lo, 1));
        mx_lo = fmaxf(mx_lo, __shfl_xor_sync(0xffffffffu, mx_lo, 2));
        mx_hi = fmaxf(mx_hi, __shfl_xor_sync(0xffffffffu, mx_hi, 1));
        mx_hi = fmaxf(mx_hi, __shfl_xor_sync(0xffffffffu, mx_hi, 2));

        float nm_lo = fmaxf(m_lo, mx_lo), nm_hi = fmaxf(m_hi, mx_hi);
        float corr_lo = __expf(m_lo - nm_lo), corr_hi = __expf(m_hi - nm_hi);
        m_lo = nm_lo; m_hi = nm_hi;

        float rs_lo = 0.f, rs_hi = 0.f;
        #pragma unroll
        for (int nf = 0; nf < 8; nf++) {
            sacc[nf][0] = __expf(sacc[nf][0] - nm_lo);
            sacc[nf][1] = __expf(sacc[nf][1] - nm_lo);
            sacc[nf][2] = __expf(sacc[nf][2] - nm_hi);
            sacc[nf][3] = __expf(sacc[nf][3] - nm_hi);
            rs_lo += sacc[nf][0] + sacc[nf][1];
            rs_hi += sacc[nf][2] + sacc[nf][3];
        }
        rs_lo += __shfl_xor_sync(0xffffffffu, rs_lo, 1);
        rs_lo += __shfl_xor_sync(0xffffffffu, rs_lo, 2);
        rs_hi += __shfl_xor_sync(0xffffffffu, rs_hi, 1);
        rs_hi += __shfl_xor_sync(0xffffffffu, rs_hi, 2);
        l_lo = l_lo * corr_lo + rs_lo;
        l_hi = l_hi * corr_hi + rs_hi;

        #pragma unroll
        for (int nf = 0; nf < 8; nf++) {
            oacc[nf][0] *= corr_lo; oacc[nf][1] *= corr_lo;
            oacc[nf][2] *= corr_hi; oacc[nf][3] *= corr_hi;
        }

        int lane0 = 4 * g + (tig >> 1);
        int lane2 = lane0 + 2;
        bool odd = (tig & 1);
        #pragma unroll
        for (int ks2 = 0; ks2 < 8; ks2++) {
            float w00 = __shfl_sync(0xffffffffu, sacc[ks2][0], lane0);
            float w01 = __shfl_sync(0xffffffffu, sacc[ks2][1], lane0);
            float w10 = __shfl_sync(0xffffffffu, sacc[ks2][2], lane0);
            float w11 = __shfl_sync(0xffffffffu, sacc[ks2][3], lane0);
            float w20 = __shfl_sync(0xffffffffu, sacc[ks2][0], lane2);
            float w21 = __shfl_sync(0xffffffffu, sacc[ks2][1], lane2);
            float w30 = __shfl_sync(0xffffffffu, sacc[ks2][2], lane2);
            float w31 = __shfl_sync(0xffffffffu, sacc[ks2][3], lane2);
            unsigned af[4];
            af[0] = __float_as_uint(odd ? w01 : w00);
            af[1] = __float_as_uint(odd ? w11 : w10);
            af[2] = __float_as_uint(odd ? w21 : w20);
            af[3] = __float_as_uint(odd ? w31 : w30);
            #pragma unroll
            for (int nf = 0; nf < 8; nf++) {
                unsigned b0 = __float_as_uint(vs_[(ks2 * 8 + tig) * VLD + nf * 8 + g]);
                unsigned b1 = __float_as_uint(vs_[(ks2 * 8 + tig + 4) * VLD + nf * 8 + g]);
                MMA_TF32(oacc[nf], af, b0, b1);
            }
        }
        __syncthreads();
    }

    float inv_lo = 1.f / l_lo, inv_hi = 1.f / l_hi;
    float* O = ap.O;
    #pragma unroll
    for (int nf = 0; nf < 8; nf++) {
        int col = h * Ddim + nf * 8 + 2 * tig;
        *(float2*)(O + ((size_t)(b * Sdim + qr + g)) * Edim + col) =
            make_float2(oacc[nf][0] * inv_lo, oacc[nf][1] * inv_lo);
        *(float2*)(O + ((size_t)(b * Sdim + qr + g + 8)) * Edim + col) =
            make_float2(oacc[nf][2] * inv_hi, oacc[nf][3] * inv_hi);
    }
}

// ---------------- fused add+LN, both streams, vectorized ----------------
// grid 2*NTOK, 128 threads. out = LN(a+b)*scale+bias
struct LnP { const float* a; const float* b; const float* scale; const float* bias; float* out; };
struct LnP2 { LnP p[2]; };

__global__ __launch_bounds__(128) void add_ln2(LnP2 pp)
{
    __shared__ float red[8];
    LnP p = pp.p[blockIdx.x >> 12];
    int tok = blockIdx.x & (NTOK - 1);
    int t = threadIdx.x;
    size_t base4 = (size_t)tok * (Edim / 4) + t;

    float4 av = ((const float4*)p.a)[base4];
    float4 bv = ((const float4*)p.b)[base4];
    float x0 = av.x + bv.x, x1 = av.y + bv.y, x2 = av.z + bv.z, x3 = av.w + bv.w;

    float s1 = x0 + x1 + x2 + x3;
    float s2 = x0 * x0 + x1 * x1 + x2 * x2 + x3 * x3;
    block_sum2_128(s1, s2, red);

    float mu = s1 * (1.f / Edim);
    float var = s2 * (1.f / Edim) - mu * mu;
    float r = rsqrtf(var + 1e-5f);

    float4 sc = ((const float4*)p.scale)[t];
    float4 bi = ((const float4*)p.bias)[t];
    float4 o;
    o.x = (x0 - mu) * r * sc.x + bi.x;
    o.y = (x1 - mu) * r * sc.y + bi.y;
    o.z = (x2 - mu) * r * sc.z + bi.z;
    o.w = (x3 - mu) * r * sc.w + bi.w;
    ((float4*)p.out)[base4] = o;
}

// ---------------- fused gate+mix+LN, both streams, vectorized ----------------
struct GateP { const float* x; const float* xc; float* out; };
struct GateP2 {
    GateP p[2];
    const float* gw; const float* gb; const float* scale; const float* bias;
};

__global__ __launch_bounds__(128) void gate_mix_ln2(GateP2 pp)
{
    __shared__ float red[8];
    GateP p = pp.p[blockIdx.x >> 12];
    int tok = blockIdx.x & (NTOK - 1);
    int t = threadIdx.x;
    size_t base4 = (size_t)tok * (Edim / 4) + t;

    float4 xv = ((const float4*)p.x)[base4];
    float4 cv = ((const float4*)p.xc)[base4];

    // gate logits: rows 4t..4t+3 pair with x, rows 512+4t..512+4t+3 with xc
    const float4* gw4 = (const float4*)pp.gw;
    float4 ga = gw4[t * 2];        // gw rows 4t,4t+1 (2 floats each)
    float4 gb_ = gw4[t * 2 + 1];   // rows 4t+2,4t+3
    float4 gc = gw4[256 + t * 2];      // rows 512+4t..
    float4 gd = gw4[256 + t * 2 + 1];

    float l0 = xv.x * ga.x + xv.y * ga.z + xv.z * gb_.x + xv.w * gb_.z
             + cv.x * gc.x + cv.y * gc.z + cv.z * gd.x + cv.w * gd.z;
    float l1 = xv.x * ga.y + xv.y * ga.w + xv.z * gb_.y + xv.w * gb_.w
             + cv.x * gc.y + cv.y * gc.w + cv.z * gd.y + cv.w * gd.w;
    block_sum2_128(l0, l1, red);
    l0 += pp.gb[0]; l1 += pp.gb[1];

    float mx = fmaxf(l0, l1);
    float e0 = __expf(l0 - mx), e1 = __expf(l1 - mx);
    float g0 = e0 / (e0 + e1), g1 = 1.f - g0;

    float m0 = xv.x * g0 + cv.x * g1;
    float m1 = xv.y * g0 + cv.y * g1;
    float m2 = xv.z * g0 + cv.z * g1;
    float m3 = xv.w * g0 + cv.w * g1;

    float s1 = m0 + m1 + m2 + m3;
    float s2 = m0 * m0 + m1 * m1 + m2 * m2 + m3 * m3;
    block_sum2_128(s1, s2, red);

    float mu = s1 * (1.f / Edim);
    float var = s2 * (1.f / Edim) - mu * mu;
    float r = rsqrtf(var + 1e-5f);

    float4 sc = ((const float4*)pp.scale)[t];
    float4 bi = ((const float4*)pp.bias)[t];
    float4 o;
    o.x = (m0 - mu) * r * sc.x + bi.x;
    o.y = (m1 - mu) * r * sc.y + bi.y;
    o.z = (m2 - mu) * r * sc.z + bi.z;
    o.w = (m3 - mu) * r * sc.w + bi.w;
    ((float4*)p.out)[base4] = o;
}

// ---------------- host side ----------------
#define GEMM_SMEM_128 71680
#define GEMM_SMEM_64  53248
#define ATTN_SMEM 71680

extern "C" void kernel_launch(void* const* d_in, const int* in_sizes, int n_in,
                              void* d_out, int out_size)
{
    const float* body_feats = (const float*)d_in[0];
    const float* limb_feats = (const float*)d_in[1];
    const float* qw = (const float*)d_in[2];
    const float* qb = (const float*)d_in[3];
    const float* kw = (const float*)d_in[4];
    const float* kb = (const float*)d_in[5];
    const float* vw = (const float*)d_in[6];
    const float* vb = (const float*)d_in[7];
    const float* ow = (const float*)d_in[8];
    const float* ob = (const float*)d_in[9];
    const float* w1 = (const float*)d_in[10];
    const float* b1 = (const float*)d_in[11];
    const float* w2 = (const float*)d_in[12];
    const float* b2 = (const float*)d_in[13];
    const float* ns = (const float*)d_in[14];
    const float* nb = (const float*)d_in[15];
    const float* gw = (const float*)d_in[16];
    const float* gb = (const float*)d_in[17];
    const void*  temp = d_in[18];

    cudaFuncSetAttribute(gemm_tc<128>, cudaFuncAttributeMaxDynamicSharedMemorySize, GEMM_SMEM_128);
    cudaFuncSetAttribute(gemm_tc<64>,  cudaFuncAttributeMaxDynamicSharedMemorySize, GEMM_SMEM_64);
    cudaFuncSetAttribute(attention_tc, cudaFuncAttributeMaxDynamicSharedMemorySize, ATTN_SMEM);

    float *q, *k, *v, *q2, *k2, *v2, *attn, *attn2, *proj, *proj2;
    float *body1, *limb1, *bcross, *lcross, *body2, *limb2, *mid, *mid2;
    cudaGetSymbolAddress((void**)&q, g_q);
    cudaGetSymbolAddress((void**)&k, g_k);
    cudaGetSymbolAddress((void**)&v, g_v);
    cudaGetSymbolAddress((void**)&q2, g_q2);
    cudaGetSymbolAddress((void**)&k2, g_k2);
    cudaGetSymbolAddress((void**)&v2, g_v2);
    cudaGetSymbolAddress((void**)&attn, g_attn);
    cudaGetSymbolAddress((void**)&attn2, g_attn2);
    cudaGetSymbolAddress((void**)&proj, g_proj);
    cudaGetSymbolAddress((void**)&proj2, g_proj2);
    cudaGetSymbolAddress((void**)&body1, g_body1);
    cudaGetSymbolAddress((void**)&limb1, g_limb1);
    cudaGetSymbolAddress((void**)&bcross, g_bcross);
    cudaGetSymbolAddress((void**)&lcross, g_lcross);
    cudaGetSymbolAddress((void**)&body2, g_body2);
    cudaGetSymbolAddress((void**)&limb2, g_limb2);
    cudaGetSymbolAddress((void**)&mid, g_mid);
    cudaGetSymbolAddress((void**)&mid2, g_mid2);

    float* out_body = (float*)d_out;
    float* out_limb = (float*)d_out + (size_t)NTOK * Edim;

    const size_t EE = (size_t)Edim * Edim;
    dim3 agrid(Bdim * NHdim, Sdim / 64, 2);

    // ===== self attention stage =====
    {
        GemmB6 bt;
        bt.g[0] = { body_feats, qw + 0 * EE, qb + 0 * Edim, q };
        bt.g[1] = { body_feats, kw + 0 * EE, kb + 0 * Edim, k };
        bt.g[2] = { body_feats, vw + 0 * EE, vb + 0 * Edim, v };
        bt.g[3] = { limb_feats, qw + 1 * EE, qb + 1 * Edim, q2 };
        bt.g[4] = { limb_feats, kw + 1 * EE, kb + 1 * Edim, k2 };
        bt.g[5] = { limb_feats, vw + 1 * EE, vb + 1 * Edim, v2 };
        gemm_tc<128><<<dim3(Edim / 128, NTOK / 128, 6), 256, GEMM_SMEM_128>>>(bt, NTOK, Edim, Edim, 0);
    }
    {
        AttnB2 at;
        at.a[0] = { q, k, v, attn };
        at.a[1] = { q2, k2, v2, attn2 };
        attention_tc<<<agrid, 128, ATTN_SMEM>>>(at, temp);
    }
    {
        GemmB6 bt;
        bt.g[0] = { attn,  ow + 0 * EE, ob + 0 * Edim, proj };
        bt.g[1] = { attn2, ow + 1 * EE, ob + 1 * Edim, proj2 };
        bt.g[2] = bt.g[0]; bt.g[3] = bt.g[0]; bt.g[4] = bt.g[0]; bt.g[5] = bt.g[0];
        gemm_tc<64><<<dim3(Edim / 128, NTOK / 64, 2), 128, GEMM_SMEM_64>>>(bt, NTOK, Edim, Edim, 0);
    }
    {
        LnP2 lp;
        lp.p[0] = { body_feats, proj,  ns + 0 * Edim, nb + 0 * Edim, body1 };
        lp.p[1] = { limb_feats, proj2, ns + 3 * Edim, nb + 3 * Edim, limb1 };
        add_ln2<<<2 * NTOK, 128>>>(lp);
    }

    // ===== cross attention stage =====
    {
        GemmB6 bt;
        bt.g[0] = { body1, qw + 2 * EE, qb + 2 * Edim, q };
        bt.g[1] = { limb1, kw + 2 * EE, kb + 2 * Edim, k };
        bt.g[2] = { limb1, vw + 2 * EE, vb + 2 * Edim, v };
        bt.g[3] = { limb1, qw + 3 * EE, qb + 3 * Edim, q2 };
        bt.g[4] = { body1, kw + 3 * EE, kb + 3 * Edim, k2 };
        bt.g[5] = { body1, vw + 3 * EE, vb + 3 * Edim, v2 };
        gemm_tc<128><<<dim3(Edim / 128, NTOK / 128, 6), 256, GEMM_SMEM_128>>>(bt, NTOK, Edim, Edim, 0);
    }
    {
        AttnB2 at;
        at.a[0] = { q, k, v, attn };
        at.a[1] = { q2, k2, v2, attn2 };
        attention_tc<<<agrid, 128, ATTN_SMEM>>>(at, temp);
    }
    {
        GemmB6 bt;
        bt.g[0] = { attn,  ow + 2 * EE, ob + 2 * Edim, bcross };
        bt.g[1] = { attn2, ow + 3 * EE, ob + 3 * Edim, lcross };
        bt.g[2] = bt.g[0]; bt.g[3] = bt.g[0]; bt.g[4] = bt.g[0]; bt.g[5] = bt.g[0];
        gemm_tc<64><<<dim3(Edim / 128, NTOK / 64, 2), 128, GEMM_SMEM_64>>>(bt, NTOK, Edim, Edim, 0);
    }

    // ===== gates + mix + LN (norm index 1 for BOTH streams, faithful) =====
    {
        GateP2 gp;
        gp.p[0] = { body1, bcross, body2 };
        gp.p[1] = { limb1, lcross, limb2 };
        gp.gw = gw; gp.gb = gb; gp.scale = ns + 1 * Edim; gp.bias = nb + 1 * Edim;
        gate_mix_ln2<<<2 * NTOK, 128>>>(gp);
    }

    // ===== FFN + final LN =====
    {
        GemmB6 bt;
        bt.g[0] = { body2, w1, b1, mid };
        bt.g[1] = { limb2, w1 + (size_t)Edim * E4, b1 + E4, mid2 };
        bt.g[2] = bt.g[0]; bt.g[3] = bt.g[0]; bt.g[4] = bt.g[0]; bt.g[5] = bt.g[0];
        gemm_tc<128><<<dim3(E4 / 128, NTOK / 128, 2), 256, GEMM_SMEM_128>>>(bt, NTOK, E4, Edim, 1);
    }
    {
        GemmB6 bt;
        bt.g[0] = { mid,  w2, b2, proj };
        bt.g[1] = { mid2, w2 + (size_t)E4 * Edim, b2 + Edim, proj2 };
        bt.g[2] = bt.g[0]; bt.g[3] = bt.g[0]; bt.g[4] = bt.g[0]; bt.g[5] = bt.g[0];
        gemm_tc<64><<<dim3(Edim / 128, NTOK / 64, 2), 128, GEMM_SMEM_64>>>(bt, NTOK, Edim, E4, 0);
    }
    {
        LnP2 lp;
        lp.p[0] = { body2, proj,  ns + 2 * Edim, nb + 2 * Edim, out_body };
        lp.p[1] = { limb2, proj2, ns + 5 * Edim, nb + 5 * Edim, out_limb };
        add_ln2<<<2 * NTOK, 128>>>(lp);
    }
}

// round 13
// speedup vs baseline: 1.0517x; 1.0517x over previous
#include <cuda_runtime.h>
#include <cuda_bf16.h>
#include <math.h>

// Problem constants
#define Bdim 4
#define Sdim 1024
#define Edim 512
#define NHdim 8
#define Ddim 64
#define NTOK (Bdim * Sdim)        // 4096
#define E4 (4 * Edim)             // 2048

// ---------------- scratch (device globals; allocation-free) ----------------
__device__ float g_q[NTOK * Edim];
__device__ float g_k[NTOK * Edim];
__device__ float g_v[NTOK * Edim];
__device__ float g_q2[NTOK * Edim];
__device__ float g_k2[NTOK * Edim];
__device__ float g_v2[NTOK * Edim];
__device__ float g_attn[NTOK * Edim];
__device__ float g_attn2[NTOK * Edim];
__device__ float g_proj[NTOK * Edim];
__device__ float g_proj2[NTOK * Edim];
__device__ float g_body1[NTOK * Edim];
__device__ float g_limb1[NTOK * Edim];
__device__ float g_bcross[NTOK * Edim];
__device__ float g_lcross[NTOK * Edim];
__device__ float g_body2[NTOK * Edim];
__device__ float g_limb2[NTOK * Edim];
__device__ float g_mid[NTOK * E4];
__device__ float g_mid2[NTOK * E4];

// ---------------- helpers ----------------
__device__ __forceinline__ float read_temp(const void* p) {
    int iv = *(const int*)p;
    float fv = __int_as_float(iv);
    if (iv > 0 && iv < 0x00800000) return (float)iv;  // int bit pattern
    return fv;
}

__device__ __forceinline__ unsigned f2tf32(float f) {
    unsigned u;
    asm("cvt.rna.tf32.f32 %0, %1;" : "=r"(u) : "f"(f));
    return u;
}

__device__ __forceinline__ void cp16(void* dst, const void* src) {
    unsigned d = (unsigned)__cvta_generic_to_shared(dst);
    asm volatile("cp.async.cg.shared.global [%0], [%1], 16;\n" :: "r"(d), "l"(src));
}
__device__ __forceinline__ void cp_commit() {
    asm volatile("cp.async.commit_group;\n");
}
template<int N> __device__ __forceinline__ void cp_wait() {
    asm volatile("cp.async.wait_group %0;\n" :: "n"(N));
}

// reduce two values across a 128-thread block (4 warps)
__device__ __forceinline__ void block_sum2_128(float& a, float& b, float* red) {
    #pragma unroll
    for (int s = 16; s > 0; s >>= 1) {
        a += __shfl_xor_sync(0xffffffffu, a, s);
        b += __shfl_xor_sync(0xffffffffu, b, s);
    }
    int wid = threadIdx.x >> 5, lane = threadIdx.x & 31;
    if (lane == 0) { red[wid] = a; red[4 + wid] = b; }
    __syncthreads();
    a = red[0] + red[1] + red[2] + red[3];
    b = red[4] + red[5] + red[6] + red[7];
    __syncthreads();
}

#define MMA_TF32(ACC, AF, B0, B1)                                              \
    asm volatile(                                                              \
        "mma.sync.aligned.m16n8k8.row.col.f32.tf32.tf32.f32 "                  \
        "{%0,%1,%2,%3}, {%4,%5,%6,%7}, {%8,%9}, {%0,%1,%2,%3};\n"              \
        : "+f"((ACC)[0]), "+f"((ACC)[1]), "+f"((ACC)[2]), "+f"((ACC)[3])       \
        : "r"((AF)[0]), "r"((AF)[1]), "r"((AF)[2]), "r"((AF)[3]),              \
          "r"(B0), "r"(B1))

// ---------------- batched TF32 GEMM: C[M,N] = A @ W + bias (+opt GELU) ----------------
// 128x128x32 tile, 256 thr = 8 warps (4M x 2N), warp tile 32x64, double-buffered cp.async.
struct GemmB { const float* A; const float* W; const float* bias; float* C; };
struct GemmB6 { GemmB g[6]; };

#define GSM_BUF 8960
#define GLA 36
#define GLB 136

__global__ __launch_bounds__(256) void gemm_tc(
    GemmB6 batch, int M, int N, int K, int act)
{
    extern __shared__ float sm[];
    GemmB gp = batch.g[blockIdx.z];
    const float* __restrict__ A = gp.A;
    const float* __restrict__ W = gp.W;

    int tid = threadIdx.x;
    int lane = tid & 31;
    int warp = tid >> 5;
    int g = lane >> 2;
    int tig = lane & 3;

    int row0 = blockIdx.y * 128;
    int col0 = blockIdx.x * 128;
    int wm0 = (warp >> 1) * 32;
    int wn0 = (warp & 1) * 64;

    float acc[2][8][4];
    #pragma unroll
    for (int mf = 0; mf < 2; mf++)
        #pragma unroll
        for (int nf = 0; nf < 8; nf++)
            #pragma unroll
            for (int r = 0; r < 4; r++) acc[mf][nf][r] = 0.f;

    int a_r = tid >> 3, a_c4 = tid & 7;
    int b_k = tid >> 5, b_c4 = tid & 31;

    int nkt = K / 32;

    {
        float* as = sm;
        float* bs = sm + 128 * GLA;
        #pragma unroll
        for (int it = 0; it < 4; it++)
            cp16(as + (a_r + it * 32) * GLA + a_c4 * 4,
                 A + (size_t)(row0 + a_r + it * 32) * K + a_c4 * 4);
        #pragma unroll
        for (int it = 0; it < 4; it++)
            cp16(bs + (b_k + it * 8) * GLB + b_c4 * 4,
                 W + (size_t)(b_k + it * 8) * N + col0 + b_c4 * 4);
        cp_commit();
    }

    for (int kt = 0; kt < nkt; kt++) {
        if (kt + 1 < nkt) {
            int k0 = (kt + 1) * 32;
            float* as = sm + ((kt + 1) & 1) * GSM_BUF;
            float* bs = as + 128 * GLA;
            #pragma unroll
            for (int it = 0; it < 4; it++)
                cp16(as + (a_r + it * 32) * GLA + a_c4 * 4,
                     A + (size_t)(row0 + a_r + it * 32) * K + k0 + a_c4 * 4);
            #pragma unroll
            for (int it = 0; it < 4; it++)
                cp16(bs + (b_k + it * 8) * GLB + b_c4 * 4,
                     W + (size_t)(k0 + b_k + it * 8) * N + col0 + b_c4 * 4);
            cp_commit();
            cp_wait<1>();
        } else {
            cp_wait<0>();
        }
        __syncthreads();

        const float* as = sm + (kt & 1) * GSM_BUF;
        const float* bs = as + 128 * GLA;

        #pragma unroll
        for (int ks = 0; ks < 4; ks++) {
            int kk = ks * 8;
            unsigned a_frag[2][4];
            #pragma unroll
            for (int mf = 0; mf < 2; mf++) {
                int rb = wm0 + mf * 16;
                a_frag[mf][0] = __float_as_uint(as[(rb + g) * GLA + kk + tig]);
                a_frag[mf][1] = __float_as_uint(as[(rb + g + 8) * GLA + kk + tig]);
                a_frag[mf][2] = __float_as_uint(as[(rb + g) * GLA + kk + tig + 4]);
                a_frag[mf][3] = __float_as_uint(as[(rb + g + 8) * GLA + kk + tig + 4]);
            }
            unsigned b_frag[8][2];
            #pragma unroll
            for (int nf = 0; nf < 8; nf++) {
                int c = wn0 + nf * 8 + g;
                b_frag[nf][0] = __float_as_uint(bs[(kk + tig) * GLB + c]);
                b_frag[nf][1] = __float_as_uint(bs[(kk + tig + 4) * GLB + c]);
            }
            #pragma unroll
            for (int mf = 0; mf < 2; mf++)
                #pragma unroll
                for (int nf = 0; nf < 8; nf++)
                    MMA_TF32(acc[mf][nf], a_frag[mf], b_frag[nf][0], b_frag[nf][1]);
        }
        __syncthreads();
    }

    const float* bias = gp.bias;
    float* C = gp.C;
    #pragma unroll
    for (int mf = 0; mf < 2; mf++) {
        #pragma unroll
        for (int nf = 0; nf < 8; nf++) {
            int col = col0 + wn0 + nf * 8 + tig * 2;
            float bx = bias[col], by = bias[col + 1];
            float v0 = acc[mf][nf][0] + bx;
            float v1 = acc[mf][nf][1] + by;
            float v2 = acc[mf][nf][2] + bx;
            float v3 = acc[mf][nf][3] + by;
            if (act == 1) {
                v0 = 0.5f * v0 * (1.f + erff(v0 * 0.70710678118f));
                v1 = 0.5f * v1 * (1.f + erff(v1 * 0.70710678118f));
                v2 = 0.5f * v2 * (1.f + erff(v2 * 0.70710678118f));
                v3 = 0.5f * v3 * (1.f + erff(v3 * 0.70710678118f));
            }
            int r = row0 + wm0 + mf * 16 + g;
            *(float2*)(C + (size_t)r * N + col) = make_float2(v0, v1);
            *(float2*)(C + (size_t)(r + 8) * N + col) = make_float2(v2, v3);
        }
    }
}

// ---------------- batched tensor-core flash attention ----------------
struct AttnB { const float* Q; const float* K; const float* V; float* O; };
struct AttnB2 { AttnB a[2]; };

#define KLD 68
#define VLD 72

__global__ __launch_bounds__(128) void attention_tc(
    AttnB2 batch, const void* __restrict__ temp_ptr)
{
    extern __shared__ float sm[];
    AttnB ap = batch.a[blockIdx.z];
    const float* __restrict__ Q = ap.Q;
    const float* __restrict__ K = ap.K;
    const float* __restrict__ V = ap.V;

    int bh = blockIdx.x;
    int b = bh >> 3, h = bh & 7;
    int tid = threadIdx.x, lane = tid & 31, warp = tid >> 5;
    int g = lane >> 2, tig = lane & 3;
    int qr = blockIdx.y * 64 + warp * 16;

    float scale = 0.125f / read_temp(temp_ptr);

    unsigned qf[8][4];
    {
        const float* Qb = Q + ((size_t)(b * Sdim + qr)) * Edim + h * Ddim;
        #pragma unroll
        for (int ks = 0; ks < 8; ks++) {
            qf[ks][0] = f2tf32(Qb[(size_t)g * Edim + ks * 8 + tig] * scale);
            qf[ks][1] = f2tf32(Qb[(size_t)(g + 8) * Edim + ks * 8 + tig] * scale);
            qf[ks][2] = f2tf32(Qb[(size_t)g * Edim + ks * 8 + tig + 4] * scale);
            qf[ks][3] = f2tf32(Qb[(size_t)(g + 8) * Edim + ks * 8 + tig + 4] * scale);
        }
    }

    float oacc[8][4];
    #pragma unroll
    for (int nf = 0; nf < 8; nf++)
        #pragma unroll
        for (int r = 0; r < 4; r++) oacc[nf][r] = 0.f;

    float m_lo = -1e30f, m_hi = -1e30f, l_lo = 0.f, l_hi = 0.f;

    int st_r = tid >> 4;
    int st_c4 = tid & 15;

    {
        float* ks_ = sm;
        float* vs_ = sm + 8704;
        #pragma unroll
        for (int it = 0; it < 8; it++) {
            int r = st_r + it * 8;
            size_t base = ((size_t)(b * Sdim + r)) * Edim + h * Ddim + st_c4 * 4;
            cp16(ks_ + r * KLD + st_c4 * 4, K + base);
            cp16(vs_ + r * VLD + st_c4 * 4, V + base);
        }
        cp_commit();
    }

    const int NKT = Sdim / 64;
    for (int kt = 0; kt < NKT; kt++) {
        if (kt + 1 < NKT) {
            float* ks_ = sm + ((kt + 1) & 1) * 4352;
            float* vs_ = sm + 8704 + ((kt + 1) & 1) * 4608;
            #pragma unroll
            for (int it = 0; it < 8; it++) {
                int r = st_r + it * 8;
                size_t base = ((size_t)(b * Sdim + (kt + 1) * 64 + r)) * Edim + h * Ddim + st_c4 * 4;
                cp16(ks_ + r * KLD + st_c4 * 4, K + base);
                cp16(vs_ + r * VLD + st_c4 * 4, V + base);
            }
            cp_commit();
            cp_wait<1>();
        } else {
            cp_wait<0>();
        }
        __syncthreads();

        const float* ks_ = sm + (kt & 1) * 4352;
        const float* vs_ = sm + 8704 + (kt & 1) * 4608;

        float sacc[8][4];
        #pragma unroll
        for (int nf = 0; nf < 8; nf++) {
            #pragma unroll
            for (int r = 0; r < 4; r++) sacc[nf][r] = 0.f;
            int krow = nf * 8 + g;
            #pragma unroll
            for (int ks = 0; ks < 8; ks++) {
                unsigned b0 = __float_as_uint(ks_[krow * KLD + ks * 8 + tig]);
                unsigned b1 = __float_as_uint(ks_[krow * KLD + ks * 8 + tig + 4]);
                MMA_TF32(sacc[nf], qf[ks], b0, b1);
            }
        }

        float mx_lo = -1e30f, mx_hi = -1e30f;
        #pragma unroll
        for (int nf = 0; nf < 8; nf++) {
            mx_lo = fmaxf(mx_lo, fmaxf(sacc[nf][0], sacc[nf][1]));
            mx_hi = fmaxf(mx_hi, fmaxf(sacc[nf][2], sacc[nf][3]));
        }
        mx_lo = fmaxf(mx_lo, __shfl_xor_sync(0xffffffffu, mx_lo, 1));
        mx_lo = fmaxf(mx_lo, __shfl_xor_sync(0xffffffffu, mx_lo, 2));
        mx_hi = fmaxf(mx_hi, __shfl_xor_sync(0xffffffffu, mx_hi, 1));
        mx_hi = fmaxf(mx_hi, __shfl_xor_sync(0xffffffffu, mx_hi, 2));

        float nm_lo = fmaxf(m_lo, mx_lo), nm_hi = fmaxf(m_hi, mx_hi);
        float corr_lo = __expf(m_lo - nm_lo), corr_hi = __expf(m_hi - nm_hi);
        m_lo = nm_lo; m_hi = nm_hi;

        float rs_lo = 0.f, rs_hi = 0.f;
        #pragma unroll
        for (int nf = 0; nf < 8; nf++) {
            sacc[nf][0] = __expf(sacc[nf][0] - nm_lo);
            sacc[nf][1] = __expf(sacc[nf][1] - nm_lo);
            sacc[nf][2] = __expf(sacc[nf][2] - nm_hi);
            sacc[nf][3] = __expf(sacc[nf][3] - nm_hi);
            rs_lo += sacc[nf][0] + sacc[nf][1];
            rs_hi += sacc[nf][2] + sacc[nf][3];
        }
        rs_lo += __shfl_xor_sync(0xffffffffu, rs_lo, 1);
        rs_lo += __shfl_xor_sync(0xffffffffu, rs_lo, 2);
        rs_hi += __shfl_xor_sync(0xffffffffu, rs_hi, 1);
        rs_hi += __shfl_xor_sync(0xffffffffu, rs_hi, 2);
        l_lo = l_lo * corr_lo + rs_lo;
        l_hi = l_hi * corr_hi + rs_hi;

        #pragma unroll
        for (int nf = 0; nf < 8; nf++) {
            oacc[nf][0] *= corr_lo; oacc[nf][1] *= corr_lo;
            oacc[nf][2] *= corr_hi; oacc[nf][3] *= corr_hi;
        }

        int lane0 = 4 * g + (tig >> 1);
        int lane2 = lane0 + 2;
        bool odd = (tig & 1);
        #pragma unroll
        for (int ks2 = 0; ks2 < 8; ks2++) {
            float w00 = __shfl_sync(0xffffffffu, sacc[ks2][0], lane0);
            float w01 = __shfl_sync(0xffffffffu, sacc[ks2][1], lane0);
            float w10 = __shfl_sync(0xffffffffu, sacc[ks2][2], lane0);
            float w11 = __shfl_sync(0xffffffffu, sacc[ks2][3], lane0);
            float w20 = __shfl_sync(0xffffffffu, sacc[ks2][0], lane2);
            float w21 = __shfl_sync(0xffffffffu, sacc[ks2][1], lane2);
            float w30 = __shfl_sync(0xffffffffu, sacc[ks2][2], lane2);
            float w31 = __shfl_sync(0xffffffffu, sacc[ks2][3], lane2);
            unsigned af[4];
            af[0] = __float_as_uint(odd ? w01 : w00);
            af[1] = __float_as_uint(odd ? w11 : w10);
            af[2] = __float_as_uint(odd ? w21 : w20);
            af[3] = __float_as_uint(odd ? w31 : w30);
            #pragma unroll
            for (int nf = 0; nf < 8; nf++) {
                unsigned b0 = __float_as_uint(vs_[(ks2 * 8 + tig) * VLD + nf * 8 + g]);
                unsigned b1 = __float_as_uint(vs_[(ks2 * 8 + tig + 4) * VLD + nf * 8 + g]);
                MMA_TF32(oacc[nf], af, b0, b1);
            }
        }
        __syncthreads();
    }

    float inv_lo = 1.f / l_lo, inv_hi = 1.f / l_hi;
    float* O = ap.O;
    #pragma unroll
    for (int nf = 0; nf < 8; nf++) {
        int col = h * Ddim + nf * 8 + 2 * tig;
        *(float2*)(O + ((size_t)(b * Sdim + qr + g)) * Edim + col) =
            make_float2(oacc[nf][0] * inv_lo, oacc[nf][1] * inv_lo);
        *(float2*)(O + ((size_t)(b * Sdim + qr + g + 8)) * Edim + col) =
            make_float2(oacc[nf][2] * inv_hi, oacc[nf][3] * inv_hi);
    }
}

// ---------------- fused add+LN, both streams, vectorized ----------------
struct LnP { const float* a; const float* b; const float* scale; const float* bias; float* out; };
struct LnP2 { LnP p[2]; };

__global__ __launch_bounds__(128) void add_ln2(LnP2 pp)
{
    __shared__ float red[8];
    LnP p = pp.p[blockIdx.x >> 12];
    int tok = blockIdx.x & (NTOK - 1);
    int t = threadIdx.x;
    size_t base4 = (size_t)tok * (Edim / 4) + t;

    float4 av = ((const float4*)p.a)[base4];
    float4 bv = ((const float4*)p.b)[base4];
    float x0 = av.x + bv.x, x1 = av.y + bv.y, x2 = av.z + bv.z, x3 = av.w + bv.w;

    float s1 = x0 + x1 + x2 + x3;
    float s2 = x0 * x0 + x1 * x1 + x2 * x2 + x3 * x3;
    block_sum2_128(s1, s2, red);

    float mu = s1 * (1.f / Edim);
    float var = s2 * (1.f / Edim) - mu * mu;
    float r = rsqrtf(var + 1e-5f);

    float4 sc = ((const float4*)p.scale)[t];
    float4 bi = ((const float4*)p.bias)[t];
    float4 o;
    o.x = (x0 - mu) * r * sc.x + bi.x;
    o.y = (x1 - mu) * r * sc.y + bi.y;
    o.z = (x2 - mu) * r * sc.z + bi.z;
    o.w = (x3 - mu) * r * sc.w + bi.w;
    ((float4*)p.out)[base4] = o;
}

// ---------------- fused gate+mix+LN, both streams, vectorized ----------------
struct GateP { const float* x; const float* xc; float* out; };
struct GateP2 {
    GateP p[2];
    const float* gw; const float* gb; const float* scale; const float* bias;
};

__global__ __launch_bounds__(128) void gate_mix_ln2(GateP2 pp)
{
    __shared__ float red[8];
    GateP p = pp.p[blockIdx.x >> 12];
    int tok = blockIdx.x & (NTOK - 1);
    int t = threadIdx.x;
    size_t base4 = (size_t)tok * (Edim / 4) + t;

    float4 xv = ((const float4*)p.x)[base4];
    float4 cv = ((const float4*)p.xc)[base4];

    const float4* gw4 = (const float4*)pp.gw;
    float4 ga = gw4[t * 2];
    float4 gb_ = gw4[t * 2 + 1];
    float4 gc = gw4[256 + t * 2];
    float4 gd = gw4[256 + t * 2 + 1];

    float l0 = xv.x * ga.x + xv.y * ga.z + xv.z * gb_.x + xv.w * gb_.z
             + cv.x * gc.x + cv.y * gc.z + cv.z * gd.x + cv.w * gd.z;
    float l1 = xv.x * ga.y + xv.y * ga.w + xv.z * gb_.y + xv.w * gb_.w
             + cv.x * gc.y + cv.y * gc.w + cv.z * gd.y + cv.w * gd.w;
    block_sum2_128(l0, l1, red);
    l0 += pp.gb[0]; l1 += pp.gb[1];

    float mx = fmaxf(l0, l1);
    float e0 = __expf(l0 - mx), e1 = __expf(l1 - mx);
    float g0 = e0 / (e0 + e1), g1 = 1.f - g0;

    float m0 = xv.x * g0 + cv.x * g1;
    float m1 = xv.y * g0 + cv.y * g1;
    float m2 = xv.z * g0 + cv.z * g1;
    float m3 = xv.w * g0 + cv.w * g1;

    float s1 = m0 + m1 + m2 + m3;
    float s2 = m0 * m0 + m1 * m1 + m2 * m2 + m3 * m3;
    block_sum2_128(s1, s2, red);

    float mu = s1 * (1.f / Edim);
    float var = s2 * (1.f / Edim) - mu * mu;
    float r = rsqrtf(var + 1e-5f);

    float4 sc = ((const float4*)pp.scale)[t];
    float4 bi = ((const float4*)pp.bias)[t];
    float4 o;
    o.x = (m0 - mu) * r * sc.x + bi.x;
    o.y = (m1 - mu) * r * sc.y + bi.y;
    o.z = (m2 - mu) * r * sc.z + bi.z;
    o.w = (m3 - mu) * r * sc.w + bi.w;
    ((float4*)p.out)[base4] = o;
}

// ---------------- host side ----------------
#define GEMM_SMEM 71680
#define ATTN_SMEM 71680

extern "C" void kernel_launch(void* const* d_in, const int* in_sizes, int n_in,
                              void* d_out, int out_size)
{
    const float* body_feats = (const float*)d_in[0];
    const float* limb_feats = (const float*)d_in[1];
    const float* qw = (const float*)d_in[2];
    const float* qb = (const float*)d_in[3];
    const float* kw = (const float*)d_in[4];
    const float* kb = (const float*)d_in[5];
    const float* vw = (const float*)d_in[6];
    const float* vb = (const float*)d_in[7];
    const float* ow = (const float*)d_in[8];
    const float* ob = (const float*)d_in[9];
    const float* w1 = (const float*)d_in[10];
    const float* b1 = (const float*)d_in[11];
    const float* w2 = (const float*)d_in[12];
    const float* b2 = (const float*)d_in[13];
    const float* ns = (const float*)d_in[14];
    const float* nb = (const float*)d_in[15];
    const float* gw = (const float*)d_in[16];
    const float* gb = (const float*)d_in[17];
    const void*  temp = d_in[18];

    cudaFuncSetAttribute(gemm_tc, cudaFuncAttributeMaxDynamicSharedMemorySize, GEMM_SMEM);
    cudaFuncSetAttribute(attention_tc, cudaFuncAttributeMaxDynamicSharedMemorySize, ATTN_SMEM);

    float *q, *k, *v, *q2, *k2, *v2, *attn, *attn2, *proj, *proj2;
    float *body1, *limb1, *bcross, *lcross, *body2, *limb2, *mid, *mid2;
    cudaGetSymbolAddress((void**)&q, g_q);
    cudaGetSymbolAddress((void**)&k, g_k);
    cudaGetSymbolAddress((void**)&v, g_v);
    cudaGetSymbolAddress((void**)&q2, g_q2);
    cudaGetSymbolAddress((void**)&k2, g_k2);
    cudaGetSymbolAddress((void**)&v2, g_v2);
    cudaGetSymbolAddress((void**)&attn, g_attn);
    cudaGetSymbolAddress((void**)&attn2, g_attn2);
    cudaGetSymbolAddress((void**)&proj, g_proj);
    cudaGetSymbolAddress((void**)&proj2, g_proj2);
    cudaGetSymbolAddress((void**)&body1, g_body1);
    cudaGetSymbolAddress((void**)&limb1, g_limb1);
    cudaGetSymbolAddress((void**)&bcross, g_bcross);
    cudaGetSymbolAddress((void**)&lcross, g_lcross);
    cudaGetSymbolAddress((void**)&body2, g_body2);
    cudaGetSymbolAddress((void**)&limb2, g_limb2);
    cudaGetSymbolAddress((void**)&mid, g_mid);
    cudaGetSymbolAddress((void**)&mid2, g_mid2);

    float* out_body = (float*)d_out;
    float* out_limb = (float*)d_out + (size_t)NTOK * Edim;

    const size_t EE = (size_t)Edim * Edim;
    dim3 agrid(Bdim * NHdim, Sdim / 64, 2);

    // ===== self attention stage =====
    {
        GemmB6 bt;
        bt.g[0] = { body_feats, qw + 0 * EE, qb + 0 * Edim, q };
        bt.g[1] = { body_feats, kw + 0 * EE, kb + 0 * Edim, k };
        bt.g[2] = { body_feats, vw + 0 * EE, vb + 0 * Edim, v };
        bt.g[3] = { limb_feats, qw + 1 * EE, qb + 1 * Edim, q2 };
        bt.g[4] = { limb_feats, kw + 1 * EE, kb + 1 * Edim, k2 };
        bt.g[5] = { limb_feats, vw + 1 * EE, vb + 1 * Edim, v2 };
        gemm_tc<<<dim3(Edim / 128, NTOK / 128, 6), 256, GEMM_SMEM>>>(bt, NTOK, Edim, Edim, 0);
    }
    {
        AttnB2 at;
        at.a[0] = { q, k, v, attn };
        at.a[1] = { q2, k2, v2, attn2 };
        attention_tc<<<agrid, 128, ATTN_SMEM>>>(at, temp);
    }
    {
        GemmB6 bt;
        bt.g[0] = { attn,  ow + 0 * EE, ob + 0 * Edim, proj };
        bt.g[1] = { attn2, ow + 1 * EE, ob + 1 * Edim, proj2 };
        bt.g[2] = bt.g[0]; bt.g[3] = bt.g[0]; bt.g[4] = bt.g[0]; bt.g[5] = bt.g[0];
        gemm_tc<<<dim3(Edim / 128, NTOK / 128, 2), 256, GEMM_SMEM>>>(bt, NTOK, Edim, Edim, 0);
    }
    {
        LnP2 lp;
        lp.p[0] = { body_feats, proj,  ns + 0 * Edim, nb + 0 * Edim, body1 };
        lp.p[1] = { limb_feats, proj2, ns + 3 * Edim, nb + 3 * Edim, limb1 };
        add_ln2<<<2 * NTOK, 128>>>(lp);
    }

    // ===== cross attention stage =====
    {
        GemmB6 bt;
        bt.g[0] = { body1, qw + 2 * EE, qb + 2 * Edim, q };
        bt.g[1] = { limb1, kw + 2 * EE, kb + 2 * Edim, k };
        bt.g[2] = { limb1, vw + 2 * EE, vb + 2 * Edim, v };
        bt.g[3] = { limb1, qw + 3 * EE, qb + 3 * Edim, q2 };
        bt.g[4] = { body1, kw + 3 * EE, kb + 3 * Edim, k2 };
        bt.g[5] = { body1, vw + 3 * EE, vb + 3 * Edim, v2 };
        gemm_tc<<<dim3(Edim / 128, NTOK / 128, 6), 256, GEMM_SMEM>>>(bt, NTOK, Edim, Edim, 0);
    }
    {
        AttnB2 at;
        at.a[0] = { q, k, v, attn };
        at.a[1] = { q2, k2, v2, attn2 };
        attention_tc<<<agrid, 128, ATTN_SMEM>>>(at, temp);
    }
    {
        GemmB6 bt;
        bt.g[0] = { attn,  ow + 2 * EE, ob + 2 * Edim, bcross };
        bt.g[1] = { attn2, ow + 3 * EE, ob + 3 * Edim, lcross };
        bt.g[2] = bt.g[0]; bt.g[3] = bt.g[0]; bt.g[4] = bt.g[0]; bt.g[5] = bt.g[0];
        gemm_tc<<<dim3(Edim / 128, NTOK / 128, 2), 256, GEMM_SMEM>>>(bt, NTOK, Edim, Edim, 0);
    }

    // ===== gates + mix + LN (norm index 1 for BOTH streams, faithful) =====
    {
        GateP2 gp;
        gp.p[0] = { body1, bcross, body2 };
        gp.p[1] = { limb1, lcross, limb2 };
        gp.gw = gw; gp.gb = gb; gp.scale = ns + 1 * Edim; gp.bias = nb + 1 * Edim;
        gate_mix_ln2<<<2 * NTOK, 128>>>(gp);
    }

    // ===== FFN + final LN =====
    {
        GemmB6 bt;
        bt.g[0] = { body2, w1, b1, mid };
        bt.g[1] = { limb2, w1 + (size_t)Edim * E4, b1 + E4, mid2 };
        bt.g[2] = bt.g[0]; bt.g[3] = bt.g[0]; bt.g[4] = bt.g[0]; bt.g[5] = bt.g[0];
        gemm_tc<<<dim3(E4 / 128, NTOK / 128, 2), 256, GEMM_SMEM>>>(bt, NTOK, E4, Edim, 1);
    }
    {
        GemmB6 bt;
        bt.g[0] = { mid,  w2, b2, proj };
        bt.g[1] = { mid2, w2 + (size_t)E4 * Edim, b2 + Edim, proj2 };
        bt.g[2] = bt.g[0]; bt.g[3] = bt.g[0]; bt.g[4] = bt.g[0]; bt.g[5] = bt.g[0];
        gemm_tc<<<dim3(Edim / 128, NTOK / 128, 2), 256, GEMM_SMEM>>>(bt, NTOK, Edim, E4, 0);
    }
    {
        LnP2 lp;
        lp.p[0] = { body2, proj,  ns + 2 * Edim, nb + 2 * Edim, out_body };
        lp.p[1] = { limb2, proj2, ns + 5 * Edim, nb + 5 * Edim, out_limb };
        add_ln2<<<2 * NTOK, 128>>>(lp);
    }
}